// round 9
// baseline (speedup 1.0000x reference)
#include <cuda_runtime.h>
#include <cuda_fp16.h>
#include <math.h>

#define HH 134
#define WW 20
#define HW 2680
#define CC 64
#define BB 128
#define NIN 21440        // CC*HW/8 groups per batch
#define NTF 8
#define RTF 17
#define NHALO 23         // RTF + 6
#define TSS 340          // RTF * WW   (K1 smem halfs per channel)
#define HSS 460          // NHALO * WW (K2 smem halfs per channel)

// ---- scratch (static device globals) ----
__device__ __half d_h[(size_t)BB * CC * HW];   // raw conv+relu, fp16, 43.9 MB
__device__ __half d_u[(size_t)BB * CC * HW];   // u = h*ca*sa, fp16, 43.9 MB
__device__ float d_psum[NTF * BB * CC];
__device__ float d_pmax[NTF * BB * CC];
__device__ float d_pu[NTF * BB * 8];           // partials of S[k] = Sum_n u[k]
__device__ float d_pscA[8 * BB * 8];
__device__ float d_pscB[8 * BB * 8];

// ---------------------------------------------------------------------------
// K1: 3x3 conv (1->64ch) + ReLU -> d_h fp16, ONCE; per-(tile,b,c) sum/max.
// grid (NTF, BB), 256 threads. dyn smem: hs = CC*TSS halfs = 43.5 KB.
// ---------------------------------------------------------------------------
__global__ void k_conv(const float* __restrict__ x,
                       const float* __restrict__ cw,
                       const float* __restrict__ cb) {
    extern __shared__ __half hs[];               // [CC][TSS] raw h fp16
    __shared__ __align__(16) float wsh[CC * 12];
    __shared__ float cbs[CC];
    __shared__ float xs[(RTF + 2) * WW];

    const int tile = blockIdx.x, b = blockIdx.y, tid = threadIdx.x;
    const int warp = tid >> 5, lane = tid & 31;
    const int r0 = tile * RTF, nr = min(RTF, HH - r0);
    const int lx0 = max(r0 - 1, 0), lx1 = min(r0 + nr + 1, HH), nlx = lx1 - lx0;

    for (int i = tid; i < CC * 12; i += 256) {
        const int c = i / 12, q = i - c * 12;
        wsh[i] = (q < 9) ? cw[c * 9 + q] : 0.f;
    }
    if (tid < CC) cbs[tid] = cb[tid];
    for (int i = tid; i < nlx * WW; i += 256) xs[i] = x[(size_t)b * HW + lx0 * WW + i];
    __syncthreads();

    // conv: thread per pixel-pair, all 64 channels
    {
        const int pairs = nr * 10;
        if (tid < pairs) {
            const int lrow = tid / 10, col2 = (tid - lrow * 10) * 2;
            const int row = r0 + lrow;
            float win[3][4];
#pragma unroll
            for (int r = 0; r < 3; r++) {
                const int ih = row - 1 + r;
                const bool vr = (ih >= lx0) && (ih < lx1);
                const int lr = ih - lx0;
#pragma unroll
                for (int q = 0; q < 4; q++) {
                    const int iw = col2 - 1 + q;
                    win[r][q] = (vr && (unsigned)iw < WW) ? xs[lr * WW + iw] : 0.f;
                }
            }
#pragma unroll 4
            for (int c = 0; c < CC; c++) {
                const float4 wa = *(const float4*)&wsh[c * 12];
                const float4 wb = *(const float4*)&wsh[c * 12 + 4];
                const float w8 = wsh[c * 12 + 8];
                const float bias = cbs[c];
                float h0 = bias + wa.x * win[0][0] + wa.y * win[0][1] + wa.z * win[0][2]
                                + wa.w * win[1][0] + wb.x * win[1][1] + wb.y * win[1][2]
                                + wb.z * win[2][0] + wb.w * win[2][1] + w8 * win[2][2];
                float h1 = bias + wa.x * win[0][1] + wa.y * win[0][2] + wa.z * win[0][3]
                                + wa.w * win[1][1] + wb.x * win[1][2] + wb.y * win[1][3]
                                + wb.z * win[2][1] + wb.w * win[2][2] + w8 * win[2][3];
                h0 = fmaxf(h0, 0.f);
                h1 = fmaxf(h1, 0.f);
                *(__half2*)&hs[c * TSS + lrow * WW + col2] = __floats2half2_rn(h0, h1);
            }
        }
    }
    __syncthreads();

    // per-channel stats + coalesced global write; warp w owns channels w*8..w*8+7
    {
        const int tot2 = (nr * WW) >> 1;
#pragma unroll
        for (int cc = 0; cc < 8; cc++) {
            const int c = warp * 8 + cc;
            const __half2* hrow = (const __half2*)(hs + c * TSS);
            __half2* grow = (__half2*)(d_h + (size_t)(b * CC + c) * HW + r0 * WW);
            float s = 0.f, m = 0.f;
            for (int j = lane; j < tot2; j += 32) {
                const __half2 hv = hrow[j];
                grow[j] = hv;
                const float2 f = __half22float2(hv);
                s += f.x + f.y;
                m = fmaxf(m, fmaxf(f.x, f.y));
            }
#pragma unroll
            for (int off = 16; off; off >>= 1) {
                s += __shfl_down_sync(0xffffffffu, s, off);
                m = fmaxf(m, __shfl_down_sync(0xffffffffu, m, off));
            }
            if (lane == 0) {
                d_psum[(tile * BB + b) * CC + c] = s;
                d_pmax[(tile * BB + b) * CC + c] = m;
            }
        }
    }
}

// ---------------------------------------------------------------------------
// K2: read h, fold ca, spatial attention, write u, S partials. NO conv.
// grid (NTF, BB), 256 threads. dyn smem: hs = CC*HSS halfs = 57.5 KB.
// ---------------------------------------------------------------------------
__global__ void k_fuse2(const float* __restrict__ sw,
                        const float* __restrict__ w1,
                        const float* __restrict__ w2) {
    extern __shared__ __half hs[];                // [CC][HSS] h*ca fp16
    __shared__ float cas[CC], ws[98];
    __shared__ float avg_s[CC], mx_s[CC], hid_s[8];
    __shared__ float spm[NHALO * WW], spx[NHALO * WW];
    __shared__ float sa_s[RTF * WW];
    __shared__ float red[8][8];

    const int tile = blockIdx.x, b = blockIdx.y, tid = threadIdx.x;
    const int warp = tid >> 5, lane = tid & 31;
    const int r0 = tile * RTF, nr = min(RTF, HH - r0);
    const int hs0 = max(r0 - 3, 0), hs1 = min(r0 + nr + 3, HH), nhs = hs1 - hs0;

    // ca stats + MLP
    if (tid < CC) {
        float s = 0.f, m = 0.f;
#pragma unroll
        for (int t = 0; t < NTF; t++) {
            s += d_psum[(t * BB + b) * CC + tid];
            m = fmaxf(m, d_pmax[(t * BB + b) * CC + tid]);
        }
        avg_s[tid] = s * (1.f / (float)HW);
        mx_s[tid] = m;
    }
    if (tid >= 64 && tid < 64 + 98) ws[tid - 64] = sw[tid - 64];
    __syncthreads();
    if (tid < 8) {
        const int i = tid & 3;
        const float* v = (tid < 4) ? avg_s : mx_s;
        float a = 0.f;
        for (int c = 0; c < CC; c++) a += v[c] * w1[i * CC + c];
        hid_s[tid] = fmaxf(a, 0.f);
    }
    __syncthreads();
    if (tid < CC) {
        float o = 0.f;
#pragma unroll
        for (int i = 0; i < 4; i++) o += (hid_s[i] + hid_s[4 + i]) * w2[tid * 4 + i];
        cas[tid] = 1.f / (1.f + __expf(-o));
    }
    __syncthreads();

    // stage A: load h halo tiles (coalesced), fold ca -> hs
    {
        const int tot2 = (nhs * WW) >> 1;
#pragma unroll
        for (int cc = 0; cc < 8; cc++) {
            const int c = warp * 8 + cc;
            const float cv = cas[c];
            const __half2 cav = __floats2half2_rn(cv, cv);
            const __half2* grow = (const __half2*)(d_h + (size_t)(b * CC + c) * HW + hs0 * WW);
            __half2* hrow = (__half2*)(hs + c * HSS);
            for (int j = lane; j < tot2; j += 32)
                hrow[j] = __hmul2(grow[j], cav);
        }
    }
    __syncthreads();

    // stage A2: spm/spx over halo rows from hs (LDS scan over channels)
    {
        const int pairs = nhs * 10;
        if (tid < pairs) {
            float s0 = 0.f, s1 = 0.f, m0 = -1e30f, m1 = -1e30f;
#pragma unroll 8
            for (int c = 0; c < CC; c++) {
                const float2 f = __half22float2(*(const __half2*)&hs[c * HSS + tid * 2]);
                s0 += f.x; s1 += f.y;
                m0 = fmaxf(m0, f.x); m1 = fmaxf(m1, f.y);
            }
            spm[tid * 2] = s0 * (1.f / (float)CC);
            spm[tid * 2 + 1] = s1 * (1.f / (float)CC);
            spx[tid * 2] = m0;
            spx[tid * 2 + 1] = m1;
        }
    }
    __syncthreads();

    // stage B: 7x7 conv -> sa; S partials
    float ps[8];
#pragma unroll
    for (int k = 0; k < 8; k++) ps[k] = 0.f;
    for (int p = tid; p < nr * WW; p += 256) {
        const int hh = r0 + p / WW, ww = p - (p / WW) * WW;
        float acc = 0.f;
#pragma unroll
        for (int kh = 0; kh < 7; kh++) {
            const int ih = hh + kh - 3;
            if ((unsigned)ih >= HH) continue;
            const int lrow = ih - hs0;
#pragma unroll
            for (int kw = 0; kw < 7; kw++) {
                const int iw = ww + kw - 3;
                if ((unsigned)iw >= WW) continue;
                const int q = lrow * WW + iw;
                acc += spm[q] * ws[kh * 7 + kw] + spx[q] * ws[49 + kh * 7 + kw];
            }
        }
        const float sa = 1.f / (1.f + __expf(-acc));
        sa_s[p] = sa;
        const int k = (r0 * WW + p) & 7;
        ps[k] += (float)CC * spm[(hh - hs0) * WW + ww] * sa;
    }
#pragma unroll
    for (int k = 0; k < 8; k++) {
#pragma unroll
        for (int off = 16; off; off >>= 1)
            ps[k] += __shfl_down_sync(0xffffffffu, ps[k], off);
    }
    if (lane == 0) {
#pragma unroll
        for (int k = 0; k < 8; k++) red[warp][k] = ps[k];
    }
    __syncthreads();
    if (tid < 8) {
        float s = 0.f;
#pragma unroll
        for (int w = 0; w < 8; w++) s += red[w][tid];
        d_pu[(tile * BB + b) * 8 + tid] = s;
    }

    // stage C: u = hs * sa -> global fp16, warp-per-channel coalesced
    {
        const int tot2 = (nr * WW) >> 1;
        const int off2 = ((r0 - hs0) * WW) >> 1;
#pragma unroll
        for (int cc = 0; cc < 8; cc++) {
            const int c = warp * 8 + cc;
            const __half2* hrow = (const __half2*)(hs + c * HSS) + off2;
            __half2* urow = (__half2*)(d_u + (size_t)(b * CC + c) * HW + r0 * WW);
            for (int j = lane; j < tot2; j += 32) {
                const __half2 sav = __floats2half2_rn(sa_s[2 * j], sa_s[2 * j + 1]);
                urow[j] = __hmul2(hrow[j], sav);
            }
        }
    }
}

// ---------------------------------------------------------------------------
// routing update chain (warp-wide): sc[16] -> s -> squash -> v -> g
// ---------------------------------------------------------------------------
__device__ __forceinline__ void upd_chain(const float* __restrict__ W,
                                          const float* sc, float* vs,
                                          float* g, bool add, int lane) {
    const int j = lane >> 4;
    float acc = 0.f;
#pragma unroll
    for (int k = 0; k < 8; k++) acc += sc[j * 8 + k] * W[k * 32 + lane];
    float s2 = acc * acc;
#pragma unroll
    for (int off = 8; off; off >>= 1) s2 += __shfl_xor_sync(0xffffffffu, s2, off, 16);
    s2 += 1e-8f;
    const float v = (sqrtf(s2) / (1.f + s2)) * acc;
    vs[lane] = v;
    __syncwarp();
    if (lane < 16) {
        const int jj = lane >> 3, k = lane & 7;
        float a = 0.f;
#pragma unroll
        for (int dd = 0; dd < 16; dd++) a += vs[jj * 16 + dd] * W[k * 32 + jj * 16 + dd];
        g[lane] = add ? (g[lane] + a) : a;
    }
    __syncwarp();
}

// ---------------------------------------------------------------------------
// K3: routing streaming pass, MLP-4 front-batched. grid (8,BB), 256 threads.
// ---------------------------------------------------------------------------
template <int PASS>
__global__ void k_route(const float* __restrict__ W) {
    __shared__ float Ssh[8], ash[8], sc[16], vs[32], g[16];
    __shared__ float red[8][8];
    const int chunk = blockIdx.x, b = blockIdx.y, tid = threadIdx.x;

    if (tid < 32) {
        if (tid < 8) {
            float S = 0.f;
#pragma unroll
            for (int t = 0; t < NTF; t++) S += d_pu[(t * BB + b) * 8 + tid];
            Ssh[tid] = S;
        }
        __syncwarp();
        if (tid < 16) sc[tid] = 0.5f * Ssh[tid & 7];
        __syncwarp();
        upd_chain(W, sc, vs, g, false, tid);       // g1
        if (PASS == 1) {
            if (tid < 8) {
                float a = 0.f;
#pragma unroll
                for (int ch = 0; ch < 8; ch++) a += d_pscA[(ch * BB + b) * 8 + tid];
                ash[tid] = a;
            }
            __syncwarp();
            if (tid < 16) sc[tid] = (tid < 8) ? ash[tid] : (Ssh[tid - 8] - ash[tid - 8]);
            __syncwarp();
            upd_chain(W, sc, vs, g, true, tid);    // g2
        }
    }
    __syncthreads();

    float gd[8];
#pragma unroll
    for (int k = 0; k < 8; k++) gd[k] = g[k] - g[8 + k];

    float a0[8];
#pragma unroll
    for (int k = 0; k < 8; k++) a0[k] = 0.f;

    const __half* up = d_u + (size_t)b * CC * HW;
    const int n0 = chunk * (NIN / 8), n1 = n0 + (NIN / 8);

    auto comp = [&](const uint4& raw) {
        const __half2* h2 = (const __half2*)&raw;
        float u[8];
        float2 f;
        f = __half22float2(h2[0]); u[0] = f.x; u[1] = f.y;
        f = __half22float2(h2[1]); u[2] = f.x; u[3] = f.y;
        f = __half22float2(h2[2]); u[4] = f.x; u[5] = f.y;
        f = __half22float2(h2[3]); u[6] = f.x; u[7] = f.y;
        float d = 0.f;
#pragma unroll
        for (int k = 0; k < 8; k++) d += u[k] * gd[k];
        const float c0 = 1.f / (1.f + __expf(-d));
#pragma unroll
        for (int k = 0; k < 8; k++) a0[k] += c0 * u[k];
    };

    int n = n0 + tid;
    for (; n + 768 < n1; n += 1024) {
        const uint4 r0 = *(const uint4*)(up + (size_t)n * 8);
        const uint4 r1 = *(const uint4*)(up + (size_t)(n + 256) * 8);
        const uint4 r2 = *(const uint4*)(up + (size_t)(n + 512) * 8);
        const uint4 r3 = *(const uint4*)(up + (size_t)(n + 768) * 8);
        comp(r0); comp(r1); comp(r2); comp(r3);
    }
    for (; n < n1; n += 256) {
        const uint4 r0 = *(const uint4*)(up + (size_t)n * 8);
        comp(r0);
    }

    const int warp = tid >> 5, lane = tid & 31;
#pragma unroll
    for (int k = 0; k < 8; k++) {
#pragma unroll
        for (int off = 16; off; off >>= 1)
            a0[k] += __shfl_down_sync(0xffffffffu, a0[k], off);
    }
    if (lane == 0) {
#pragma unroll
        for (int k = 0; k < 8; k++) red[warp][k] = a0[k];
    }
    __syncthreads();
    if (tid < 8) {
        float s = 0.f;
#pragma unroll
        for (int w = 0; w < 8; w++) s += red[w][tid];
        float* psc = PASS ? d_pscB : d_pscA;
        psc[(chunk * BB + b) * 8 + tid] = s;
    }
}

// ---------------------------------------------------------------------------
// K4: final lengths from pscB. grid BB, 32 threads.
// ---------------------------------------------------------------------------
__global__ void k_final(const float* __restrict__ W, float* __restrict__ out) {
    __shared__ float Ssh[8], ash[8], sc[16];
    const int b = blockIdx.x, lane = threadIdx.x;
    if (lane < 8) {
        float S = 0.f, a = 0.f;
#pragma unroll
        for (int t = 0; t < NTF; t++) S += d_pu[(t * BB + b) * 8 + lane];
#pragma unroll
        for (int ch = 0; ch < 8; ch++) a += d_pscB[(ch * BB + b) * 8 + lane];
        Ssh[lane] = S;
        ash[lane] = a;
    }
    __syncwarp();
    if (lane < 16) sc[lane] = (lane < 8) ? ash[lane] : (Ssh[lane - 8] - ash[lane - 8]);
    __syncwarp();
    const int j = lane >> 4;
    float acc = 0.f;
#pragma unroll
    for (int k = 0; k < 8; k++) acc += sc[j * 8 + k] * W[k * 32 + lane];
    float s2 = acc * acc;
#pragma unroll
    for (int off = 8; off; off >>= 1) s2 += __shfl_xor_sync(0xffffffffu, s2, off, 16);
    s2 += 1e-8f;
    const float v = (sqrtf(s2) / (1.f + s2)) * acc;
    float l2 = v * v;
#pragma unroll
    for (int off = 8; off; off >>= 1) l2 += __shfl_xor_sync(0xffffffffu, l2, off, 16);
    if ((lane & 15) == 0) out[b * 2 + j] = sqrtf(l2 + 1e-8f);
}

// ---------------------------------------------------------------------------
extern "C" void kernel_launch(void* const* d_in, const int* in_sizes, int n_in,
                              void* d_out, int out_size) {
    const float* x      = (const float*)d_in[0];
    const float* conv_w = (const float*)d_in[1];
    const float* conv_b = (const float*)d_in[2];
    const float* ca_w1  = (const float*)d_in[3];
    const float* ca_w2  = (const float*)d_in[4];
    const float* sa_w   = (const float*)d_in[5];
    const float* caps_W = (const float*)d_in[6];
    float* out = (float*)d_out;

    const int conv_smem = CC * TSS * sizeof(__half);   // 43520
    const int fuse_smem = CC * HSS * sizeof(__half);   // 58880
    cudaFuncSetAttribute(k_conv, cudaFuncAttributeMaxDynamicSharedMemorySize, conv_smem);
    cudaFuncSetAttribute(k_fuse2, cudaFuncAttributeMaxDynamicSharedMemorySize, fuse_smem);

    k_conv<<<dim3(NTF, BB), 256, conv_smem>>>(x, conv_w, conv_b);
    k_fuse2<<<dim3(NTF, BB), 256, fuse_smem>>>(sa_w, ca_w1, ca_w2);
    k_route<0><<<dim3(8, BB), 256>>>(caps_W);
    k_route<1><<<dim3(8, BB), 256>>>(caps_W);
    k_final<<<BB, 32>>>(caps_W, out);
}

// round 10
// speedup vs baseline: 1.0548x; 1.0548x over previous
#include <cuda_runtime.h>
#include <cuda_fp16.h>
#include <cuda_fp8.h>
#include <math.h>

#define HH 134
#define WW 20
#define HW 2680
#define CC 64
#define BB 128
#define NIN 21440        // CC*HW/8 groups per batch
#define NT_S 4
#define RT_S 34
#define NTF 8
#define RTF 17
#define NHALO 23         // RTF + 6
#define HSS 460          // NHALO * WW

// ---- scratch (static device globals) ----
__device__ unsigned char d_u[(size_t)BB * CC * HW];  // u fp8 e4m3, 22 MB
__device__ float d_psum[NT_S * BB * CC];
__device__ float d_pmax[NT_S * BB * CC];
__device__ float d_pu[NTF * BB * 8];                 // partials of S[k]
__device__ float d_pscA[8 * BB * 8];
__device__ float d_pscB[8 * BB * 8];

// ---------------------------------------------------------------------------
// K1: conv+relu stats only (per-(b,c) sum/max). grid (32,BB)
// ---------------------------------------------------------------------------
__global__ void k_stats(const float* __restrict__ x,
                        const float* __restrict__ cw,
                        const float* __restrict__ cb) {
    const int cg = blockIdx.x >> 2, tile = blockIdx.x & 3, b = blockIdx.y;
    const int tid = threadIdx.x;
    const int r0 = tile * RT_S, nr = min(RT_S, HH - r0);
    const int lr0 = max(r0 - 1, 0), lr1 = min(r0 + nr + 1, HH), nl = lr1 - lr0;

    __shared__ float xs[(RT_S + 2) * WW];
    __shared__ float wsh[80];
    __shared__ float red[8 * 16];

    for (int i = tid; i < nl * WW; i += 256) xs[i] = x[(size_t)b * HW + lr0 * WW + i];
    if (tid < 72) wsh[tid] = cw[cg * 72 + tid];
    if (tid >= 72 && tid < 80) wsh[tid] = cb[cg * 8 + tid - 72];
    __syncthreads();

    float wr[8][9], bsr[8];
#pragma unroll
    for (int c = 0; c < 8; c++) {
#pragma unroll
        for (int i = 0; i < 9; i++) wr[c][i] = wsh[c * 9 + i];
        bsr[c] = wsh[72 + c];
    }
    float sum[8], mx[8];
#pragma unroll
    for (int c = 0; c < 8; c++) { sum[c] = 0.f; mx[c] = 0.f; }

    for (int p = tid; p < nr * WW; p += 256) {
        const int hh = r0 + p / WW, ww = p - (p / WW) * WW;
        float win[9];
#pragma unroll
        for (int kh = 0; kh < 3; kh++) {
            const int ih = hh + kh - 1;
            const bool vr = (unsigned)ih < HH;
            const int lrow = ih - lr0;
#pragma unroll
            for (int kw = 0; kw < 3; kw++) {
                const int iw = ww + kw - 1;
                win[kh * 3 + kw] = (vr && (unsigned)iw < WW) ? xs[lrow * WW + iw] : 0.f;
            }
        }
#pragma unroll
        for (int c = 0; c < 8; c++) {
            float acc = bsr[c];
#pragma unroll
            for (int i = 0; i < 9; i++) acc += win[i] * wr[c][i];
            acc = fmaxf(acc, 0.f);
            sum[c] += acc;
            mx[c] = fmaxf(mx[c], acc);
        }
    }
    const int warp = tid >> 5, lane = tid & 31;
#pragma unroll
    for (int c = 0; c < 8; c++) {
#pragma unroll
        for (int off = 16; off; off >>= 1) {
            sum[c] += __shfl_down_sync(0xffffffffu, sum[c], off);
            mx[c] = fmaxf(mx[c], __shfl_down_sync(0xffffffffu, mx[c], off));
        }
    }
    if (lane == 0) {
#pragma unroll
        for (int c = 0; c < 8; c++) { red[warp * 16 + c] = sum[c]; red[warp * 16 + 8 + c] = mx[c]; }
    }
    __syncthreads();
    if (tid < 8) {
        float s = 0.f;
#pragma unroll
        for (int w = 0; w < 8; w++) s += red[w * 16 + tid];
        d_psum[(tile * BB + b) * CC + cg * 8 + tid] = s;
    } else if (tid < 16) {
        float m = 0.f;
#pragma unroll
        for (int w = 0; w < 8; w++) m = fmaxf(m, red[w * 16 + tid]);
        d_pmax[(tile * BB + b) * CC + cg * 8 + tid - 8] = m;
    }
}

// ---------------------------------------------------------------------------
// K2: fused ca-MLP + spatial attention + u (fp8) + S partials.
// grid (NTF,BB), 256 threads, dynamic smem 57.5 KB.
// ---------------------------------------------------------------------------
__global__ void k_fuse(const float* __restrict__ x,
                       const float* __restrict__ cw,
                       const float* __restrict__ cb,
                       const float* __restrict__ sw,
                       const float* __restrict__ w1,
                       const float* __restrict__ w2) {
    extern __shared__ __half hs[];                // [CC][HSS] h*ca fp16
    __shared__ __align__(16) float wsh[CC * 12];
    __shared__ float cbs[CC], cas[CC], ws[98];
    __shared__ float avg_s[CC], mx_s[CC], hid_s[8];
    __shared__ float xs[25 * WW];
    __shared__ float spm[NHALO * WW], spx[NHALO * WW];
    __shared__ float sa_s[RTF * WW];
    __shared__ float red[8][8];

    const int tile = blockIdx.x, b = blockIdx.y, tid = threadIdx.x;
    const int warp = tid >> 5, lane = tid & 31;
    const int r0 = tile * RTF, nr = min(RTF, HH - r0);
    const int hs0 = max(r0 - 3, 0), hs1 = min(r0 + nr + 3, HH), nhs = hs1 - hs0;
    const int lx0 = max(hs0 - 1, 0), lx1 = min(hs1 + 1, HH), nlx = lx1 - lx0;

    for (int i = tid; i < CC * 12; i += 256) {
        const int c = i / 12, q = i - c * 12;
        wsh[i] = (q < 9) ? cw[c * 9 + q] : 0.f;
    }
    if (tid < CC) {
        cbs[tid] = cb[tid];
        float s = 0.f, m = 0.f;
#pragma unroll
        for (int t = 0; t < NT_S; t++) {
            s += d_psum[(t * BB + b) * CC + tid];
            m = fmaxf(m, d_pmax[(t * BB + b) * CC + tid]);
        }
        avg_s[tid] = s * (1.f / (float)HW);
        mx_s[tid] = m;
    }
    if (tid >= 64 && tid < 64 + 98) ws[tid - 64] = sw[tid - 64];
    for (int i = tid; i < nlx * WW; i += 256) xs[i] = x[(size_t)b * HW + lx0 * WW + i];
    __syncthreads();

    if (tid < 8) {
        const int i = tid & 3;
        const float* v = (tid < 4) ? avg_s : mx_s;
        float a = 0.f;
        for (int c = 0; c < CC; c++) a += v[c] * w1[i * CC + c];
        hid_s[tid] = fmaxf(a, 0.f);
    }
    __syncthreads();
    if (tid < CC) {
        float o = 0.f;
#pragma unroll
        for (int i = 0; i < 4; i++) o += (hid_s[i] + hid_s[4 + i]) * w2[tid * 4 + i];
        cas[tid] = 1.f / (1.f + __expf(-o));
    }
    __syncthreads();

    // stage A: conv once over halo rows -> hs + spm/spx
    {
        const int pairs = nhs * 10;
        if (tid < pairs) {
            const int lrow = tid / 10, col2 = (tid - lrow * 10) * 2;
            const int row = hs0 + lrow;
            float win[3][4];
#pragma unroll
            for (int r = 0; r < 3; r++) {
                const int ih = row - 1 + r;
                const bool vr = (ih >= lx0) && (ih < lx1);
                const int lr = ih - lx0;
#pragma unroll
                for (int q = 0; q < 4; q++) {
                    const int iw = col2 - 1 + q;
                    win[r][q] = (vr && (unsigned)iw < WW) ? xs[lr * WW + iw] : 0.f;
                }
            }
            float s0 = 0.f, s1 = 0.f, m0 = -1e30f, m1 = -1e30f;
#pragma unroll 4
            for (int c = 0; c < CC; c++) {
                const float4 wa = *(const float4*)&wsh[c * 12];
                const float4 wb = *(const float4*)&wsh[c * 12 + 4];
                const float w8 = wsh[c * 12 + 8];
                const float bias = cbs[c];
                float h0 = bias + wa.x * win[0][0] + wa.y * win[0][1] + wa.z * win[0][2]
                                + wa.w * win[1][0] + wb.x * win[1][1] + wb.y * win[1][2]
                                + wb.z * win[2][0] + wb.w * win[2][1] + w8 * win[2][2];
                float h1 = bias + wa.x * win[0][1] + wa.y * win[0][2] + wa.z * win[0][3]
                                + wa.w * win[1][1] + wb.x * win[1][2] + wb.y * win[1][3]
                                + wb.z * win[2][1] + wb.w * win[2][2] + w8 * win[2][3];
                const float cv = cas[c];
                h0 = fmaxf(h0, 0.f) * cv;
                h1 = fmaxf(h1, 0.f) * cv;
                *(__half2*)&hs[c * HSS + lrow * WW + col2] = __floats2half2_rn(h0, h1);
                s0 += h0; s1 += h1;
                m0 = fmaxf(m0, h0); m1 = fmaxf(m1, h1);
            }
            const int lp = lrow * WW + col2;
            spm[lp] = s0 * (1.f / (float)CC);
            spm[lp + 1] = s1 * (1.f / (float)CC);
            spx[lp] = m0;
            spx[lp + 1] = m1;
        }
    }
    __syncthreads();

    // stage B: 7x7 conv -> sa; S partials
    float ps[8];
#pragma unroll
    for (int k = 0; k < 8; k++) ps[k] = 0.f;
    for (int p = tid; p < nr * WW; p += 256) {
        const int hh = r0 + p / WW, ww = p - (p / WW) * WW;
        float acc = 0.f;
#pragma unroll
        for (int kh = 0; kh < 7; kh++) {
            const int ih = hh + kh - 3;
            if ((unsigned)ih >= HH) continue;
            const int lrow = ih - hs0;
#pragma unroll
            for (int kw = 0; kw < 7; kw++) {
                const int iw = ww + kw - 3;
                if ((unsigned)iw >= WW) continue;
                const int q = lrow * WW + iw;
                acc += spm[q] * ws[kh * 7 + kw] + spx[q] * ws[49 + kh * 7 + kw];
            }
        }
        const float sa = 1.f / (1.f + __expf(-acc));
        sa_s[p] = sa;
        const int k = (r0 * WW + p) & 7;
        ps[k] += (float)CC * spm[(hh - hs0) * WW + ww] * sa;
    }
#pragma unroll
    for (int k = 0; k < 8; k++) {
#pragma unroll
        for (int off = 16; off; off >>= 1)
            ps[k] += __shfl_down_sync(0xffffffffu, ps[k], off);
    }
    if (lane == 0) {
#pragma unroll
        for (int k = 0; k < 8; k++) red[warp][k] = ps[k];
    }
    __syncthreads();
    if (tid < 8) {
        float s = 0.f;
#pragma unroll
        for (int w = 0; w < 8; w++) s += red[w][tid];
        d_pu[(tile * BB + b) * 8 + tid] = s;
    }

    // stage C: u = hs * sa -> global fp8 e4m3, warp-per-channel coalesced.
    // lane handles 4 consecutive pixels -> 4-byte store, 128B per warp store.
    {
        const int tot4 = (nr * WW) >> 2;
        const int off2 = ((r0 - hs0) * WW) >> 1;     // half2 units
#pragma unroll
        for (int cc = 0; cc < 8; cc++) {
            const int c = warp * 8 + cc;
            const __half2* hrow = (const __half2*)(hs + c * HSS) + off2;
            unsigned* urow = (unsigned*)(d_u + (size_t)(b * CC + c) * HW + r0 * WW);
            for (int j = lane; j < tot4; j += 32) {
                const float2 fa = __half22float2(hrow[2 * j]);
                const float2 fb = __half22float2(hrow[2 * j + 1]);
                float2 q0, q1;
                q0.x = fa.x * sa_s[4 * j];
                q0.y = fa.y * sa_s[4 * j + 1];
                q1.x = fb.x * sa_s[4 * j + 2];
                q1.y = fb.y * sa_s[4 * j + 3];
                const unsigned lo = __nv_cvt_float2_to_fp8x2(q0, __NV_SATFINITE, __NV_E4M3);
                const unsigned hi = __nv_cvt_float2_to_fp8x2(q1, __NV_SATFINITE, __NV_E4M3);
                urow[j] = (hi << 16) | lo;
            }
        }
    }
}

// ---------------------------------------------------------------------------
// routing update chain (warp-wide): sc[16] -> s -> squash -> v -> g
// ---------------------------------------------------------------------------
__device__ __forceinline__ void upd_chain(const float* __restrict__ W,
                                          const float* sc, float* vs,
                                          float* g, bool add, int lane) {
    const int j = lane >> 4;
    float acc = 0.f;
#pragma unroll
    for (int k = 0; k < 8; k++) acc += sc[j * 8 + k] * W[k * 32 + lane];
    float s2 = acc * acc;
#pragma unroll
    for (int off = 8; off; off >>= 1) s2 += __shfl_xor_sync(0xffffffffu, s2, off, 16);
    s2 += 1e-8f;
    const float v = (sqrtf(s2) / (1.f + s2)) * acc;
    vs[lane] = v;
    __syncwarp();
    if (lane < 16) {
        const int jj = lane >> 3, k = lane & 7;
        float a = 0.f;
#pragma unroll
        for (int dd = 0; dd < 16; dd++) a += vs[jj * 16 + dd] * W[k * 32 + jj * 16 + dd];
        g[lane] = add ? (g[lane] + a) : a;
    }
    __syncwarp();
}

// ---------------------------------------------------------------------------
// K3: routing streaming pass over fp8 u, MLP-4. grid (8,BB), 256 threads.
// Each 16B load = 16 fp8 = 2 groups of 8.
// ---------------------------------------------------------------------------
template <int PASS>
__global__ void k_route(const float* __restrict__ W) {
    __shared__ float Ssh[8], ash[8], sc[16], vs[32], g[16];
    __shared__ float red[8][8];
    const int chunk = blockIdx.x, b = blockIdx.y, tid = threadIdx.x;

    if (tid < 32) {
        if (tid < 8) {
            float S = 0.f;
#pragma unroll
            for (int t = 0; t < NTF; t++) S += d_pu[(t * BB + b) * 8 + tid];
            Ssh[tid] = S;
        }
        __syncwarp();
        if (tid < 16) sc[tid] = 0.5f * Ssh[tid & 7];
        __syncwarp();
        upd_chain(W, sc, vs, g, false, tid);       // g1
        if (PASS == 1) {
            if (tid < 8) {
                float a = 0.f;
#pragma unroll
                for (int ch = 0; ch < 8; ch++) a += d_pscA[(ch * BB + b) * 8 + tid];
                ash[tid] = a;
            }
            __syncwarp();
            if (tid < 16) sc[tid] = (tid < 8) ? ash[tid] : (Ssh[tid - 8] - ash[tid - 8]);
            __syncwarp();
            upd_chain(W, sc, vs, g, true, tid);    // g2
        }
    }
    __syncthreads();

    float gd[8];
#pragma unroll
    for (int k = 0; k < 8; k++) gd[k] = g[k] - g[8 + k];

    float a0[8];
#pragma unroll
    for (int k = 0; k < 8; k++) a0[k] = 0.f;

    const uint4* up4 = (const uint4*)(d_u + (size_t)b * CC * HW + (size_t)chunk * (NIN / 8) * 8);
    const int npair = NIN / 16;   // 1340 16-byte loads per chunk

    auto comp = [&](const uint4& raw) {
        const unsigned v[4] = {raw.x, raw.y, raw.z, raw.w};
        float u[16];
#pragma unroll
        for (int q = 0; q < 4; q++) {
            const __half2_raw hr0 = __nv_cvt_fp8x2_to_halfraw2(
                (__nv_fp8x2_storage_t)(v[q] & 0xffffu), __NV_E4M3);
            const __half2_raw hr1 = __nv_cvt_fp8x2_to_halfraw2(
                (__nv_fp8x2_storage_t)(v[q] >> 16), __NV_E4M3);
            const float2 f0 = __half22float2(__half2(hr0));
            const float2 f1 = __half22float2(__half2(hr1));
            u[q * 4 + 0] = f0.x; u[q * 4 + 1] = f0.y;
            u[q * 4 + 2] = f1.x; u[q * 4 + 3] = f1.y;
        }
        float d0 = 0.f, d1 = 0.f;
#pragma unroll
        for (int k = 0; k < 8; k++) { d0 += u[k] * gd[k]; d1 += u[8 + k] * gd[k]; }
        const float c0a = 1.f / (1.f + __expf(-d0));
        const float c0b = 1.f / (1.f + __expf(-d1));
#pragma unroll
        for (int k = 0; k < 8; k++) a0[k] += c0a * u[k] + c0b * u[8 + k];
    };

    int i = tid;
    for (; i + 768 < npair; i += 1024) {
        const uint4 r0 = up4[i];
        const uint4 r1 = up4[i + 256];
        const uint4 r2 = up4[i + 512];
        const uint4 r3 = up4[i + 768];
        comp(r0); comp(r1); comp(r2); comp(r3);
    }
    for (; i < npair; i += 256) {
        const uint4 r0 = up4[i];
        comp(r0);
    }

    const int warp = tid >> 5, lane = tid & 31;
#pragma unroll
    for (int k = 0; k < 8; k++) {
#pragma unroll
        for (int off = 16; off; off >>= 1)
            a0[k] += __shfl_down_sync(0xffffffffu, a0[k], off);
    }
    if (lane == 0) {
#pragma unroll
        for (int k = 0; k < 8; k++) red[warp][k] = a0[k];
    }
    __syncthreads();
    if (tid < 8) {
        float s = 0.f;
#pragma unroll
        for (int w = 0; w < 8; w++) s += red[w][tid];
        float* psc = PASS ? d_pscB : d_pscA;
        psc[(chunk * BB + b) * 8 + tid] = s;
    }
}

// ---------------------------------------------------------------------------
// K4: final lengths from pscB. grid BB, 32 threads.
// ---------------------------------------------------------------------------
__global__ void k_final(const float* __restrict__ W, float* __restrict__ out) {
    __shared__ float Ssh[8], ash[8], sc[16];
    const int b = blockIdx.x, lane = threadIdx.x;
    if (lane < 8) {
        float S = 0.f, a = 0.f;
#pragma unroll
        for (int t = 0; t < NTF; t++) S += d_pu[(t * BB + b) * 8 + lane];
#pragma unroll
        for (int ch = 0; ch < 8; ch++) a += d_pscB[(ch * BB + b) * 8 + lane];
        Ssh[lane] = S;
        ash[lane] = a;
    }
    __syncwarp();
    if (lane < 16) sc[lane] = (lane < 8) ? ash[lane] : (Ssh[lane - 8] - ash[lane - 8]);
    __syncwarp();
    const int j = lane >> 4;
    float acc = 0.f;
#pragma unroll
    for (int k = 0; k < 8; k++) acc += sc[j * 8 + k] * W[k * 32 + lane];
    float s2 = acc * acc;
#pragma unroll
    for (int off = 8; off; off >>= 1) s2 += __shfl_xor_sync(0xffffffffu, s2, off, 16);
    s2 += 1e-8f;
    const float v = (sqrtf(s2) / (1.f + s2)) * acc;
    float l2 = v * v;
#pragma unroll
    for (int off = 8; off; off >>= 1) l2 += __shfl_xor_sync(0xffffffffu, l2, off, 16);
    if ((lane & 15) == 0) out[b * 2 + j] = sqrtf(l2 + 1e-8f);
}

// ---------------------------------------------------------------------------
extern "C" void kernel_launch(void* const* d_in, const int* in_sizes, int n_in,
                              void* d_out, int out_size) {
    const float* x      = (const float*)d_in[0];
    const float* conv_w = (const float*)d_in[1];
    const float* conv_b = (const float*)d_in[2];
    const float* ca_w1  = (const float*)d_in[3];
    const float* ca_w2  = (const float*)d_in[4];
    const float* sa_w   = (const float*)d_in[5];
    const float* caps_W = (const float*)d_in[6];
    float* out = (float*)d_out;

    const int hs_bytes = CC * HSS * sizeof(__half);
    cudaFuncSetAttribute(k_fuse, cudaFuncAttributeMaxDynamicSharedMemorySize, hs_bytes);

    k_stats<<<dim3(32, BB), 256>>>(x, conv_w, conv_b);
    k_fuse<<<dim3(NTF, BB), 256, hs_bytes>>>(x, conv_w, conv_b, sa_w, ca_w1, ca_w2);
    k_route<0><<<dim3(8, BB), 256>>>(caps_W);
    k_route<1><<<dim3(8, BB), 256>>>(caps_W);
    k_final<<<BB, 32>>>(caps_W, out);
}

// round 11
// speedup vs baseline: 1.2334x; 1.1693x over previous
#include <cuda_runtime.h>
#include <cuda_fp16.h>
#include <cuda_fp8.h>
#include <math.h>

#define HH 134
#define WW 20
#define HW 2680
#define CC 64
#define BB 128
#define NIN 21440        // 8-elem groups per batch
#define NTF 8
#define RTF 17
#define NHALO 23         // RTF + 6
#define HSS 460          // NHALO * WW

// ---- scratch (static device globals) ----
__device__ unsigned char d_u[(size_t)BB * CC * HW];  // u fp8 e4m3, 22 MB
__device__ float d_psum[NTF * BB * CC];
__device__ float d_pmax[NTF * BB * CC];
__device__ float d_pu[NTF * BB * 8];                 // partials of S[k]
__device__ float d_pscA[8 * BB * 8];
__device__ float d_pscB[8 * BB * 8];
__device__ int d_cntF[BB];                           // per-batch barriers
__device__ int d_cntA[BB];
__device__ int d_cntB[BB];

// per-batch spin barrier: all global writes done before call (after __syncthreads)
__device__ __forceinline__ void batch_barrier(int* cnt, int b, int tid) {
    if (tid == 0) {
        __threadfence();
        atomicAdd(&cnt[b], 1);
        while (*((volatile int*)&cnt[b]) < 8) __nanosleep(64);
        __threadfence();
    }
    __syncthreads();
}

// ---------------------------------------------------------------------------
// K1: conv(once, halo tiles) + stats + per-batch sync + ca + spatial attn + u.
// grid (NTF, BB), 256 threads, dyn smem CC*HSS halfs = 57.5 KB.
// ---------------------------------------------------------------------------
__global__ void k_fuse_all(const float* __restrict__ x,
                           const float* __restrict__ cw,
                           const float* __restrict__ cb,
                           const float* __restrict__ sw,
                           const float* __restrict__ w1,
                           const float* __restrict__ w2) {
    extern __shared__ __half hs[];                // [CC][HSS] raw h fp16
    __shared__ __align__(16) float wsh[CC * 12];
    __shared__ float cbs[CC], cas[CC], ws[98];
    __shared__ float avg_s[CC], mx_s[CC], hid_s[8];
    __shared__ float xs[25 * WW];
    __shared__ float spm[NHALO * WW], spx[NHALO * WW];
    __shared__ float sa_s[RTF * WW];
    __shared__ float red[8][8];

    const int tile = blockIdx.x, b = blockIdx.y, tid = threadIdx.x;
    const int warp = tid >> 5, lane = tid & 31;
    const int r0 = tile * RTF, nr = min(RTF, HH - r0);
    const int hs0 = max(r0 - 3, 0), hs1 = min(r0 + nr + 3, HH), nhs = hs1 - hs0;
    const int lx0 = max(hs0 - 1, 0), lx1 = min(hs1 + 1, HH), nlx = lx1 - lx0;

    for (int i = tid; i < CC * 12; i += 256) {
        const int c = i / 12, q = i - c * 12;
        wsh[i] = (q < 9) ? cw[c * 9 + q] : 0.f;
    }
    if (tid < CC) cbs[tid] = cb[tid];
    if (tid >= 64 && tid < 64 + 98) ws[tid - 64] = sw[tid - 64];
    for (int i = tid; i < nlx * WW; i += 256) xs[i] = x[(size_t)b * HW + lx0 * WW + i];
    __syncthreads();

    // stage 1: conv RAW over halo rows -> hs
    {
        const int pairs = nhs * 10;
        if (tid < pairs) {
            const int lrow = tid / 10, col2 = (tid - lrow * 10) * 2;
            const int row = hs0 + lrow;
            float win[3][4];
#pragma unroll
            for (int r = 0; r < 3; r++) {
                const int ih = row - 1 + r;
                const bool vr = (ih >= lx0) && (ih < lx1);
                const int lr = ih - lx0;
#pragma unroll
                for (int q = 0; q < 4; q++) {
                    const int iw = col2 - 1 + q;
                    win[r][q] = (vr && (unsigned)iw < WW) ? xs[lr * WW + iw] : 0.f;
                }
            }
#pragma unroll 4
            for (int c = 0; c < CC; c++) {
                const float4 wa = *(const float4*)&wsh[c * 12];
                const float4 wb = *(const float4*)&wsh[c * 12 + 4];
                const float w8 = wsh[c * 12 + 8];
                const float bias = cbs[c];
                float h0 = bias + wa.x * win[0][0] + wa.y * win[0][1] + wa.z * win[0][2]
                                + wa.w * win[1][0] + wb.x * win[1][1] + wb.y * win[1][2]
                                + wb.z * win[2][0] + wb.w * win[2][1] + w8 * win[2][2];
                float h1 = bias + wa.x * win[0][1] + wa.y * win[0][2] + wa.z * win[0][3]
                                + wa.w * win[1][1] + wb.x * win[1][2] + wb.y * win[1][3]
                                + wb.z * win[2][1] + wb.w * win[2][2] + w8 * win[2][3];
                *(__half2*)&hs[c * HSS + lrow * WW + col2] =
                    __floats2half2_rn(fmaxf(h0, 0.f), fmaxf(h1, 0.f));
            }
        }
    }
    __syncthreads();

    // stage 2: raw-h stats over OWN rows (warp-per-channel), write partials
    {
        const int tot2 = (nr * WW) >> 1;
        const int off2 = ((r0 - hs0) * WW) >> 1;
#pragma unroll
        for (int cc = 0; cc < 8; cc++) {
            const int c = warp * 8 + cc;
            const __half2* hrow = (const __half2*)(hs + c * HSS) + off2;
            float s = 0.f, m = 0.f;
            for (int j = lane; j < tot2; j += 32) {
                const float2 f = __half22float2(hrow[j]);
                s += f.x + f.y;
                m = fmaxf(m, fmaxf(f.x, f.y));
            }
#pragma unroll
            for (int off = 16; off; off >>= 1) {
                s += __shfl_down_sync(0xffffffffu, s, off);
                m = fmaxf(m, __shfl_down_sync(0xffffffffu, m, off));
            }
            if (lane == 0) {
                d_psum[(tile * BB + b) * CC + c] = s;
                d_pmax[(tile * BB + b) * CC + c] = m;
            }
        }
    }
    __syncthreads();

    // stage 3: per-batch barrier, then ca MLP
    batch_barrier(d_cntF, b, tid);
    if (tid < CC) {
        float s = 0.f, m = 0.f;
#pragma unroll
        for (int t = 0; t < NTF; t++) {
            s += d_psum[(t * BB + b) * CC + tid];
            m = fmaxf(m, d_pmax[(t * BB + b) * CC + tid]);
        }
        avg_s[tid] = s * (1.f / (float)HW);
        mx_s[tid] = m;
    }
    __syncthreads();
    if (tid < 8) {
        const int i = tid & 3;
        const float* v = (tid < 4) ? avg_s : mx_s;
        float a = 0.f;
        for (int c = 0; c < CC; c++) a += v[c] * w1[i * CC + c];
        hid_s[tid] = fmaxf(a, 0.f);
    }
    __syncthreads();
    if (tid < CC) {
        float o = 0.f;
#pragma unroll
        for (int i = 0; i < 4; i++) o += (hid_s[i] + hid_s[4 + i]) * w2[tid * 4 + i];
        cas[tid] = 1.f / (1.f + __expf(-o));
    }
    __syncthreads();

    // stage 4: spm/spx over halo rows (ca folded in scan)
    {
        const int pairs = nhs * 10;
        if (tid < pairs) {
            float s0 = 0.f, s1 = 0.f, m0 = -1e30f, m1 = -1e30f;
#pragma unroll 8
            for (int c = 0; c < CC; c++) {
                const float2 f = __half22float2(*(const __half2*)&hs[c * HSS + tid * 2]);
                const float cv = cas[c];
                const float ax = f.x * cv, ay = f.y * cv;
                s0 += ax; s1 += ay;
                m0 = fmaxf(m0, ax); m1 = fmaxf(m1, ay);
            }
            spm[tid * 2] = s0 * (1.f / (float)CC);
            spm[tid * 2 + 1] = s1 * (1.f / (float)CC);
            spx[tid * 2] = m0;
            spx[tid * 2 + 1] = m1;
        }
    }
    __syncthreads();

    // stage 5: 7x7 conv -> sa; S partials
    float ps[8];
#pragma unroll
    for (int k = 0; k < 8; k++) ps[k] = 0.f;
    for (int p = tid; p < nr * WW; p += 256) {
        const int hh = r0 + p / WW, ww = p - (p / WW) * WW;
        float acc = 0.f;
#pragma unroll
        for (int kh = 0; kh < 7; kh++) {
            const int ih = hh + kh - 3;
            if ((unsigned)ih >= HH) continue;
            const int lrow = ih - hs0;
#pragma unroll
            for (int kw = 0; kw < 7; kw++) {
                const int iw = ww + kw - 3;
                if ((unsigned)iw >= WW) continue;
                const int q = lrow * WW + iw;
                acc += spm[q] * ws[kh * 7 + kw] + spx[q] * ws[49 + kh * 7 + kw];
            }
        }
        const float sa = 1.f / (1.f + __expf(-acc));
        sa_s[p] = sa;
        const int k = (r0 * WW + p) & 7;
        ps[k] += (float)CC * spm[(hh - hs0) * WW + ww] * sa;
    }
#pragma unroll
    for (int k = 0; k < 8; k++) {
#pragma unroll
        for (int off = 16; off; off >>= 1)
            ps[k] += __shfl_down_sync(0xffffffffu, ps[k], off);
    }
    if (lane == 0) {
#pragma unroll
        for (int k = 0; k < 8; k++) red[warp][k] = ps[k];
    }
    __syncthreads();
    if (tid < 8) {
        float s = 0.f;
#pragma unroll
        for (int w = 0; w < 8; w++) s += red[w][tid];
        d_pu[(tile * BB + b) * 8 + tid] = s;
    }

    // stage 6: u = h*ca*sa -> fp8, warp-per-channel coalesced
    {
        const int tot4 = (nr * WW) >> 2;
        const int off2 = ((r0 - hs0) * WW) >> 1;
#pragma unroll
        for (int cc = 0; cc < 8; cc++) {
            const int c = warp * 8 + cc;
            const float cv = cas[c];
            const __half2* hrow = (const __half2*)(hs + c * HSS) + off2;
            unsigned* urow = (unsigned*)(d_u + (size_t)(b * CC + c) * HW + r0 * WW);
            for (int j = lane; j < tot4; j += 32) {
                const float2 fa = __half22float2(hrow[2 * j]);
                const float2 fb = __half22float2(hrow[2 * j + 1]);
                float2 q0, q1;
                q0.x = fa.x * (cv * sa_s[4 * j]);
                q0.y = fa.y * (cv * sa_s[4 * j + 1]);
                q1.x = fb.x * (cv * sa_s[4 * j + 2]);
                q1.y = fb.y * (cv * sa_s[4 * j + 3]);
                const unsigned lo = __nv_cvt_float2_to_fp8x2(q0, __NV_SATFINITE, __NV_E4M3);
                const unsigned hi = __nv_cvt_float2_to_fp8x2(q1, __NV_SATFINITE, __NV_E4M3);
                urow[j] = (hi << 16) | lo;
            }
        }
    }
}

// ---------------------------------------------------------------------------
// routing update chain (warp-wide): sc[16] -> s -> squash -> v -> g
// ---------------------------------------------------------------------------
__device__ __forceinline__ void upd_chain(const float* __restrict__ W,
                                          const float* sc, float* vs,
                                          float* g, bool add, int lane) {
    const int j = lane >> 4;
    float acc = 0.f;
#pragma unroll
    for (int k = 0; k < 8; k++) acc += sc[j * 8 + k] * W[k * 32 + lane];
    float s2 = acc * acc;
#pragma unroll
    for (int off = 8; off; off >>= 1) s2 += __shfl_xor_sync(0xffffffffu, s2, off, 16);
    s2 += 1e-8f;
    const float v = (sqrtf(s2) / (1.f + s2)) * acc;
    vs[lane] = v;
    __syncwarp();
    if (lane < 16) {
        const int jj = lane >> 3, k = lane & 7;
        float a = 0.f;
#pragma unroll
        for (int dd = 0; dd < 16; dd++) a += vs[jj * 16 + dd] * W[k * 32 + jj * 16 + dd];
        g[lane] = add ? (g[lane] + a) : a;
    }
    __syncwarp();
}

// ---------------------------------------------------------------------------
// K2: BOTH routing passes + final, with per-batch barriers. grid (8,BB), 256.
// ---------------------------------------------------------------------------
__global__ void k_route_all(const float* __restrict__ W, float* __restrict__ out) {
    __shared__ float Ssh[8], ash[8], sc[16], vs[32], g[16];
    __shared__ float red[8][8];
    __shared__ int lastflag;
    const int chunk = blockIdx.x, b = blockIdx.y, tid = threadIdx.x;
    const int warp = tid >> 5, lane = tid & 31;

    // g1 from S
    if (tid < 32) {
        if (tid < 8) {
            float S = 0.f;
#pragma unroll
            for (int t = 0; t < NTF; t++) S += d_pu[(t * BB + b) * 8 + tid];
            Ssh[tid] = S;
        }
        __syncwarp();
        if (tid < 16) sc[tid] = 0.5f * Ssh[tid & 7];
        __syncwarp();
        upd_chain(W, sc, vs, g, false, tid);
    }
    __syncthreads();

    const uint4* up4 = (const uint4*)(d_u + (size_t)b * CC * HW + (size_t)chunk * (NIN / 8) * 8);
    const int npair = NIN / 16;

    float gd[8], a0[8];

    auto stream_pass = [&]() {
#pragma unroll
        for (int k = 0; k < 8; k++) a0[k] = 0.f;
        auto comp = [&](const uint4& raw) {
            const unsigned v[4] = {raw.x, raw.y, raw.z, raw.w};
            float u[16];
#pragma unroll
            for (int q = 0; q < 4; q++) {
                const __half2_raw hr0 = __nv_cvt_fp8x2_to_halfraw2(
                    (__nv_fp8x2_storage_t)(v[q] & 0xffffu), __NV_E4M3);
                const __half2_raw hr1 = __nv_cvt_fp8x2_to_halfraw2(
                    (__nv_fp8x2_storage_t)(v[q] >> 16), __NV_E4M3);
                const float2 f0 = __half22float2(__half2(hr0));
                const float2 f1 = __half22float2(__half2(hr1));
                u[q * 4 + 0] = f0.x; u[q * 4 + 1] = f0.y;
                u[q * 4 + 2] = f1.x; u[q * 4 + 3] = f1.y;
            }
            float d0 = 0.f, d1 = 0.f;
#pragma unroll
            for (int k = 0; k < 8; k++) { d0 += u[k] * gd[k]; d1 += u[8 + k] * gd[k]; }
            const float c0a = 1.f / (1.f + __expf(-d0));
            const float c0b = 1.f / (1.f + __expf(-d1));
#pragma unroll
            for (int k = 0; k < 8; k++) a0[k] += c0a * u[k] + c0b * u[8 + k];
        };
        int i = tid;
        for (; i + 768 < npair; i += 1024) {
            const uint4 r0 = up4[i];
            const uint4 r1 = up4[i + 256];
            const uint4 r2 = up4[i + 512];
            const uint4 r3 = up4[i + 768];
            comp(r0); comp(r1); comp(r2); comp(r3);
        }
        for (; i < npair; i += 256) {
            const uint4 r0 = up4[i];
            comp(r0);
        }
#pragma unroll
        for (int k = 0; k < 8; k++) {
#pragma unroll
            for (int off = 16; off; off >>= 1)
                a0[k] += __shfl_down_sync(0xffffffffu, a0[k], off);
        }
        if (lane == 0) {
#pragma unroll
            for (int k = 0; k < 8; k++) red[warp][k] = a0[k];
        }
        __syncthreads();
    };

    // ---- pass A ----
#pragma unroll
    for (int k = 0; k < 8; k++) gd[k] = g[k] - g[8 + k];
    stream_pass();
    if (tid < 8) {
        float s = 0.f;
#pragma unroll
        for (int w = 0; w < 8; w++) s += red[w][tid];
        d_pscA[(chunk * BB + b) * 8 + tid] = s;
    }
    __syncthreads();
    batch_barrier(d_cntA, b, tid);

    // g2 = g1 + dW(pscA)
    if (tid < 32) {
        if (tid < 8) {
            float a = 0.f;
#pragma unroll
            for (int ch = 0; ch < 8; ch++) a += d_pscA[(ch * BB + b) * 8 + tid];
            ash[tid] = a;
        }
        __syncwarp();
        if (tid < 16) sc[tid] = (tid < 8) ? ash[tid] : (Ssh[tid - 8] - ash[tid - 8]);
        __syncwarp();
        upd_chain(W, sc, vs, g, true, tid);
    }
    __syncthreads();

    // ---- pass B ----
#pragma unroll
    for (int k = 0; k < 8; k++) gd[k] = g[k] - g[8 + k];
    stream_pass();
    if (tid < 8) {
        float s = 0.f;
#pragma unroll
        for (int w = 0; w < 8; w++) s += red[w][tid];
        d_pscB[(chunk * BB + b) * 8 + tid] = s;
    }
    __syncthreads();

    // last block of this batch computes final lengths + resets counters
    if (tid == 0) {
        __threadfence();
        lastflag = (atomicAdd(&d_cntB[b], 1) == 7) ? 1 : 0;
    }
    __syncthreads();
    if (lastflag) {
        if (tid < 32) {
            __threadfence();
            if (tid < 8) {
                float a = 0.f;
#pragma unroll
                for (int ch = 0; ch < 8; ch++) a += d_pscB[(ch * BB + b) * 8 + tid];
                ash[tid] = a;
            }
            __syncwarp();
            if (tid < 16) sc[tid] = (tid < 8) ? ash[tid] : (Ssh[tid - 8] - ash[tid - 8]);
            __syncwarp();
            const int j = tid >> 4;
            float acc = 0.f;
#pragma unroll
            for (int k = 0; k < 8; k++) acc += sc[j * 8 + k] * W[k * 32 + tid];
            float s2 = acc * acc;
#pragma unroll
            for (int off = 8; off; off >>= 1) s2 += __shfl_xor_sync(0xffffffffu, s2, off, 16);
            s2 += 1e-8f;
            const float v = (sqrtf(s2) / (1.f + s2)) * acc;
            float l2 = v * v;
#pragma unroll
            for (int off = 8; off; off >>= 1) l2 += __shfl_xor_sync(0xffffffffu, l2, off, 16);
            if ((tid & 15) == 0) out[b * 2 + j] = sqrtf(l2 + 1e-8f);
        }
        __syncthreads();
        if (tid == 0) {   // reset per-batch counters for next graph replay
            d_cntF[b] = 0;
            d_cntA[b] = 0;
            d_cntB[b] = 0;
        }
    }
}

// ---------------------------------------------------------------------------
extern "C" void kernel_launch(void* const* d_in, const int* in_sizes, int n_in,
                              void* d_out, int out_size) {
    const float* x      = (const float*)d_in[0];
    const float* conv_w = (const float*)d_in[1];
    const float* conv_b = (const float*)d_in[2];
    const float* ca_w1  = (const float*)d_in[3];
    const float* ca_w2  = (const float*)d_in[4];
    const float* sa_w   = (const float*)d_in[5];
    const float* caps_W = (const float*)d_in[6];
    float* out = (float*)d_out;

    const int hs_bytes = CC * HSS * sizeof(__half);
    cudaFuncSetAttribute(k_fuse_all, cudaFuncAttributeMaxDynamicSharedMemorySize, hs_bytes);

    k_fuse_all<<<dim3(NTF, BB), 256, hs_bytes>>>(x, conv_w, conv_b, sa_w, ca_w1, ca_w2);
    k_route_all<<<dim3(8, BB), 256>>>(caps_W, out);
}